// round 13
// baseline (speedup 1.0000x reference)
#include <cuda_runtime.h>
#include <cuda_fp16.h>
#include <cstdint>

// ---------------- problem constants ----------------
#define B_        8
#define S_        1024
#define D_        4096
#define DV_       1024
#define IMG_      336
#define PATCH_    14
#define GRID_     24
#define NP_       576
#define MAXE_     1599
#define KPATCH_   588
#define M_        (B_*NP_)    // 4608
#define IMAGE_TOKEN_ 32000

#define OFF_EMB   1LL
#define N_EMB     ((long long)B_*MAXE_*D_)
#define OFF_ATTN  (OFF_EMB + N_EMB)
#define OFF_LAB   (OFF_ATTN + (long long)B_*MAXE_)
#define OFF_ROUT  (OFF_LAB  + (long long)B_*MAXE_)
#define N_TAIL    (32LL*MAXE_*8 + 32LL*MAXE_*2)

// ---------------- device scratch ----------------
__device__ __half g_hH[(size_t)M_ * DV_];    // patch-embed output (fp16)
__device__ __half g_gH[(size_t)M_ * D_];     // gelu output (fp16)
__device__ __half g_w1H[(size_t)DV_ * D_];   // w1 fp16, same [k][n] layout
__device__ __half g_w2H[(size_t)D_ * D_];    // w2 fp16, same [k][n] layout
__device__ int    g_spos[B_];

__device__ __forceinline__ float gelu_tanh(float x) {
    float x3 = x * x * x;
    return 0.5f * x * (1.0f + tanhf(0.7978845608028654f * (x + 0.044715f * x3)));
}

__device__ __forceinline__ uint32_t s2u(const void* p) {
    return (uint32_t)__cvta_generic_to_shared(p);
}
__device__ __forceinline__ void ldmx4(uint32_t* r, uint32_t addr) {
    asm volatile("ldmatrix.sync.aligned.m8n8.x4.shared.b16 {%0,%1,%2,%3}, [%4];"
                 : "=r"(r[0]), "=r"(r[1]), "=r"(r[2]), "=r"(r[3]) : "r"(addr) : "memory");
}
__device__ __forceinline__ void ldmx4t(uint32_t* r, uint32_t addr) {
    asm volatile("ldmatrix.sync.aligned.m8n8.x4.trans.shared.b16 {%0,%1,%2,%3}, [%4];"
                 : "=r"(r[0]), "=r"(r[1]), "=r"(r[2]), "=r"(r[3]) : "r"(addr) : "memory");
}
__device__ __forceinline__ void mma_f16(float* c, const uint32_t* a, const uint32_t* b) {
    asm volatile(
        "mma.sync.aligned.m16n8k16.row.col.f32.f16.f16.f32 "
        "{%0,%1,%2,%3}, {%4,%5,%6,%7}, {%8,%9}, {%0,%1,%2,%3};"
        : "+f"(c[0]), "+f"(c[1]), "+f"(c[2]), "+f"(c[3])
        : "r"(a[0]), "r"(a[1]), "r"(a[2]), "r"(a[3]), "r"(b[0]), "r"(b[1]));
}

// ---------------- small kernels (R1-proven) ----------------
__global__ void k_fill(float* __restrict__ out) {
    long long i = (long long)blockIdx.x * blockDim.x + threadIdx.x;
    if (i == 0) out[0] = 0.0f;
    if (i < B_) g_spos[i] = S_;
    long long stride = (long long)gridDim.x * blockDim.x;
    for (long long j = i; j < N_TAIL; j += stride)
        out[OFF_ROUT + j] = 0.0f;
}

__global__ void k_spos(const int* __restrict__ ids) {
    int i = blockIdx.x * blockDim.x + threadIdx.x;
    if (i < B_ * S_ && ids[i] == IMAGE_TOKEN_)
        atomicMin(&g_spos[i / S_], i % S_);
}

__global__ void k_text(const int* __restrict__ ids, const int* __restrict__ mask,
                       const int* __restrict__ labels, const float* __restrict__ table,
                       float* __restrict__ out) {
    int bs = blockIdx.x;
    int b = bs / S_, s = bs - b * S_;
    int id = ids[bs];
    if (id == IMAGE_TOKEN_) return;
    int sp = g_spos[b];
    int dest = s + (s > sp ? (NP_ - 1) : 0);
    const float* __restrict__ src = table + (long long)id * D_;
    float* __restrict__ dst = out + OFF_EMB + ((long long)b * MAXE_ + dest) * D_;
    for (int j = threadIdx.x; j < D_; j += blockDim.x)
        dst[j] = src[j];
    if (threadIdx.x == 0) {
        out[OFF_ATTN + (long long)b * MAXE_ + dest] = (float)mask[bs];
        out[OFF_LAB  + (long long)b * MAXE_ + dest] = (float)labels[bs];
    }
}

__global__ void k_imgmeta(float* __restrict__ out) {
    int i = blockIdx.x * blockDim.x + threadIdx.x;
    if (i >= B_ * NP_) return;
    int b = i / NP_, t = i - b * NP_;
    int dest = g_spos[b] + t;
    out[OFF_ATTN + (long long)b * MAXE_ + dest] = 1.0f;
    out[OFF_LAB  + (long long)b * MAXE_ + dest] = -100.0f;
}

// ---------------- fp32 -> fp16 weight conversion (elementwise) ----------------
__global__ void k_convh(const float* __restrict__ src, __half* __restrict__ dst, int n4) {
    int i = blockIdx.x * blockDim.x + threadIdx.x;
    long long stride = (long long)gridDim.x * blockDim.x;
    for (long long j = i; j < n4; j += stride) {
        float4 v = *(const float4*)(src + j * 4);
        __half2 a = __floats2half2_rn(v.x, v.y);
        __half2 b = __floats2half2_rn(v.z, v.w);
        uint2 pk = make_uint2(*(uint32_t*)&a, *(uint32_t*)&b);
        *(uint2*)(dst + j * 4) = pk;
    }
}

// ---------------- patch-embed GEMM (R1-proven math, fp16 output) ----------------
__global__ void __launch_bounds__(256)
k_patch(const float* __restrict__ pix, const float* __restrict__ Bw,
        const float* __restrict__ bias) {
    __shared__ float As[16][132];
    __shared__ float Bs[16][132];
    int t  = threadIdx.x;
    int m0 = blockIdx.y * 128;
    int n0 = blockIdx.x * 128;
    float acc[8][8] = {};
    int brow = t >> 5, bcol = t & 31;
    int rm = (t >> 4) * 8, rn = (t & 15) * 8;

    for (int k0 = 0; k0 < KPATCH_; k0 += 16) {
        #pragma unroll
        for (int i = 0; i < 8; i++) {
            int idx = t + 256 * i;
            int r  = idx >> 4;
            int kk = idx & 15;
            int k  = k0 + kk;
            float v = 0.0f;
            if (k < KPATCH_) {
                int m  = m0 + r;
                int ni = m / NP_;
                int tt = m - ni * NP_;
                int gi = tt / GRID_, gj = tt - gi * GRID_;
                int c  = k / 196;
                int rem = k - c * 196;
                int pi = rem / PATCH_, pj = rem - pi * PATCH_;
                long long addr = (((long long)ni * 3 + c) * IMG_ + gi * PATCH_ + pi) * IMG_
                               + gj * PATCH_ + pj;
                v = pix[addr];
            }
            As[kk][r] = v;
        }
        #pragma unroll
        for (int i = 0; i < 2; i++) {
            int kk = brow + i * 8;
            int k  = k0 + kk;
            float4 v = make_float4(0.f, 0.f, 0.f, 0.f);
            if (k < KPATCH_)
                v = *(const float4*)(Bw + (long long)k * DV_ + n0 + bcol * 4);
            *(float4*)(&Bs[kk][bcol * 4]) = v;
        }
        __syncthreads();
        #pragma unroll
        for (int k = 0; k < 16; k++) {
            float ra[8], rb[8];
            #pragma unroll
            for (int i = 0; i < 8; i++) ra[i] = As[k][rm + i];
            #pragma unroll
            for (int j = 0; j < 8; j++) rb[j] = Bs[k][rn + j];
            #pragma unroll
            for (int i = 0; i < 8; i++)
                #pragma unroll
                for (int j = 0; j < 8; j++)
                    acc[i][j] += ra[i] * rb[j];
        }
        __syncthreads();
    }
    #pragma unroll
    for (int i = 0; i < 8; i++) {
        int m = m0 + rm + i;
        #pragma unroll
        for (int j = 0; j < 8; j++) {
            int n = n0 + rn + j;
            g_hH[(size_t)m * DV_ + n] = __float2half(acc[i][j] + bias[n]);
        }
    }
}

// ---------------- TC GEMM — fp16-resident operands, K-chunk 32 ----------------
// fp16 global sources (no cvt in loop), 24KB static smem, register prefetch,
// R11-proven pipeline shape. CTA 128(M) x 256(N), 8 warps 2x4, warp tile 64x64.
// A smem: 128 rows x 64B, XOR key ((row>>1)&3)<<4 (bank-verified for STS.128 + ldmatrix).
// B smem: 32 k-rows x 512B, XOR key (k&7)*16 (R8/R11-proven pattern).
template<int EPI>
__global__ void __launch_bounds__(256)
k_tc(const float* __restrict__ bias, float* __restrict__ out) {
    constexpr int K = (EPI == 1) ? DV_ : D_;
    const __half* __restrict__ A  = (EPI == 1) ? g_hH : g_gH;
    const __half* __restrict__ WH = (EPI == 1) ? g_w1H : g_w2H;

    __shared__ __align__(16) char sa[8192];    // 128 rows x 64B
    __shared__ __align__(16) char sb[16384];   // 32 k-rows x 512B

    const int t = threadIdx.x, l = t & 31, wid = t >> 5;
    const int wm = wid >> 2, wn = wid & 3;
    const int m0 = blockIdx.y * 128;
    const int n0 = blockIdx.x * 256;

    float acc[4][8][4] = {};

    // register staging: A 2 x uint4, B 4 x uint4 per thread
    uint4 ra[2], rb[4];

    auto ldregs = [&](int kc) {
        #pragma unroll
        for (int i = 0; i < 2; i++) {
            int idx = t + 256 * i;
            int row = idx >> 2, seg = idx & 3;
            ra[i] = *(const uint4*)(A + (size_t)(m0 + row) * K + kc + seg * 8);
        }
        #pragma unroll
        for (int i = 0; i < 4; i++) {
            int idx = t + 256 * i;
            int k = idx >> 5, seg = idx & 31;
            rb[i] = *(const uint4*)(WH + (size_t)(kc + k) * D_ + n0 + seg * 8);
        }
    };
    auto stregs = [&]() {
        #pragma unroll
        for (int i = 0; i < 2; i++) {
            int idx = t + 256 * i;
            int row = idx >> 2, seg = idx & 3;
            uint32_t off = row * 64 + ((seg * 16) ^ (((row >> 1) & 3) << 4));
            *(uint4*)(sa + off) = ra[i];
        }
        #pragma unroll
        for (int i = 0; i < 4; i++) {
            int idx = t + 256 * i;
            int k = idx >> 5, seg = idx & 31;
            uint32_t off = k * 512 + ((seg * 16) ^ ((k & 7) * 16));
            *(uint4*)(sb + off) = rb[i];
        }
    };

    const int frow = l & 15, kb = ((l >> 4) & 1) * 16;
    const int bg = l >> 3, br = l & 7;
    const int bk = (bg & 1) * 8 + br;
    const int bnb = (bg >> 1) * 8;

    auto compute = [&]() {
        #pragma unroll
        for (int ks = 0; ks < 2; ks++) {
            uint32_t ah[4][4];
            #pragma unroll
            for (int mi = 0; mi < 4; mi++) {
                int row = wm * 64 + mi * 16 + frow;
                uint32_t off = row * 64 + ((ks * 32 + kb) ^ (((row >> 1) & 3) << 4));
                ldmx4(ah[mi], s2u(sa) + off);
            }
            #pragma unroll
            for (int p = 0; p < 4; p++) {
                int nb = wn * 64 + p * 16 + bnb;
                int kr = ks * 16 + bk;
                uint32_t o = kr * 512 + ((nb * 2) ^ ((bk & 7) * 16));
                uint32_t rh[4];
                ldmx4t(rh, s2u(sb) + o);
                uint32_t b0[2] = { rh[0], rh[1] }, b1[2] = { rh[2], rh[3] };
                #pragma unroll
                for (int mi = 0; mi < 4; mi++) {
                    mma_f16(acc[mi][2*p],   ah[mi], b0);
                    mma_f16(acc[mi][2*p+1], ah[mi], b1);
                }
            }
        }
    };

    const int nch = K / 32;
    ldregs(0);
    for (int c = 0; c < nch; c++) {
        stregs();
        __syncthreads();
        if (c + 1 < nch) ldregs((c + 1) * 32);
        compute();
        __syncthreads();
    }

    // epilogue — EPI==2 rows start at OFF_EMB=1 (odd float offset): scalar stores only.
    const int lrow = l >> 2, lcol = (l & 3) * 2;
    #pragma unroll
    for (int mi = 0; mi < 4; mi++) {
        #pragma unroll
        for (int part = 0; part < 2; part++) {
            int m = m0 + wm * 64 + mi * 16 + lrow + part * 8;
            long long rowbase;
            if (EPI == 2) {
                int bb = m / NP_;
                int tt = m - bb * NP_;
                rowbase = OFF_EMB + ((long long)bb * MAXE_ + g_spos[bb] + tt) * (long long)D_;
            } else {
                rowbase = (long long)m * D_;
            }
            #pragma unroll
            for (int nj = 0; nj < 8; nj++) {
                int n = n0 + wn * 64 + nj * 8 + lcol;
                float v0 = acc[mi][nj][part * 2 + 0] + bias[n];
                float v1 = acc[mi][nj][part * 2 + 1] + bias[n + 1];
                if (EPI == 1) {
                    __half2 hh = __floats2half2_rn(gelu_tanh(v0), gelu_tanh(v1));
                    *(__half2*)&g_gH[rowbase + n] = hh;
                } else {
                    out[rowbase + n]     = v0;
                    out[rowbase + n + 1] = v1;
                }
            }
        }
    }
}

// ---------------- launch ----------------
extern "C" void kernel_launch(void* const* d_in, const int* in_sizes, int n_in,
                              void* d_out, int out_size) {
    const int*   ids     = (const int*)  d_in[0];
    const float* pix     = (const float*)d_in[1];
    const int*   mask    = (const int*)  d_in[2];
    const int*   labels  = (const int*)  d_in[3];
    const float* table   = (const float*)d_in[4];
    const float* patch_w = (const float*)d_in[6];
    const float* patch_b = (const float*)d_in[7];
    const float* w1      = (const float*)d_in[8];
    const float* b1      = (const float*)d_in[9];
    const float* w2      = (const float*)d_in[10];
    const float* b2      = (const float*)d_in[11];
    float* out = (float*)d_out;

    __half *w1H, *w2H;
    cudaGetSymbolAddress((void**)&w1H, g_w1H);
    cudaGetSymbolAddress((void**)&w2H, g_w2H);

    k_fill<<<512, 256>>>(out);
    k_spos<<<(B_ * S_ + 255) / 256, 256>>>(ids);
    k_text<<<B_ * S_, 256>>>(ids, mask, labels, table, out);
    k_imgmeta<<<(B_ * NP_ + 255) / 256, 256>>>(out);

    k_convh<<<2048, 256>>>(w1, w1H, (DV_ * D_) / 4);
    k_convh<<<8192, 256>>>(w2, w2H, (D_ * D_) / 4);

    k_patch<<<dim3(DV_ / 128, M_ / 128), 256>>>(pix, patch_w, patch_b);
    k_tc<1><<<dim3(D_ / 256, M_ / 128), 256>>>(b1, out);
    k_tc<2><<<dim3(D_ / 256, M_ / 128), 256>>>(b2, out);
}

// round 14
// speedup vs baseline: 1.6150x; 1.6150x over previous
#include <cuda_runtime.h>
#include <cuda_fp16.h>
#include <cstdint>

// ---------------- problem constants ----------------
#define B_        8
#define S_        1024
#define D_        4096
#define DV_       1024
#define IMG_      336
#define PATCH_    14
#define GRID_     24
#define NP_       576
#define MAXE_     1599
#define KPATCH_   588
#define M_        (B_*NP_)    // 4608
#define IMAGE_TOKEN_ 32000

#define OFF_EMB   1LL
#define N_EMB     ((long long)B_*MAXE_*D_)
#define OFF_ATTN  (OFF_EMB + N_EMB)
#define OFF_LAB   (OFF_ATTN + (long long)B_*MAXE_)
#define OFF_ROUT  (OFF_LAB  + (long long)B_*MAXE_)
#define N_TAIL    (32LL*MAXE_*8 + 32LL*MAXE_*2)

// ---------------- device scratch ----------------
__device__ __half g_hH[(size_t)M_ * DV_];    // patch-embed output (fp16)
__device__ __half g_gH[(size_t)M_ * D_];     // gelu output (fp16)
__device__ __half g_w1H[(size_t)DV_ * D_];   // w1 fp16, [k][n]
__device__ __half g_w2H[(size_t)D_ * D_];    // w2 fp16, [k][n]
__device__ int    g_spos[B_];

__device__ __forceinline__ float gelu_tanh(float x) {
    float x3 = x * x * x;
    return 0.5f * x * (1.0f + tanhf(0.7978845608028654f * (x + 0.044715f * x3)));
}

__device__ __forceinline__ uint32_t s2u(const void* p) {
    return (uint32_t)__cvta_generic_to_shared(p);
}
__device__ __forceinline__ void cpasync16(uint32_t dst, const void* src) {
    asm volatile("cp.async.cg.shared.global [%0], [%1], 16;" :: "r"(dst), "l"(src) : "memory");
}
__device__ __forceinline__ void ldmx4(uint32_t* r, uint32_t addr) {
    asm volatile("ldmatrix.sync.aligned.m8n8.x4.shared.b16 {%0,%1,%2,%3}, [%4];"
                 : "=r"(r[0]), "=r"(r[1]), "=r"(r[2]), "=r"(r[3]) : "r"(addr) : "memory");
}
__device__ __forceinline__ void ldmx4t(uint32_t* r, uint32_t addr) {
    asm volatile("ldmatrix.sync.aligned.m8n8.x4.trans.shared.b16 {%0,%1,%2,%3}, [%4];"
                 : "=r"(r[0]), "=r"(r[1]), "=r"(r[2]), "=r"(r[3]) : "r"(addr) : "memory");
}
__device__ __forceinline__ void mma_f16(float* c, const uint32_t* a, const uint32_t* b) {
    asm volatile(
        "mma.sync.aligned.m16n8k16.row.col.f32.f16.f16.f32 "
        "{%0,%1,%2,%3}, {%4,%5,%6,%7}, {%8,%9}, {%0,%1,%2,%3};"
        : "+f"(c[0]), "+f"(c[1]), "+f"(c[2]), "+f"(c[3])
        : "r"(a[0]), "r"(a[1]), "r"(a[2]), "r"(a[3]), "r"(b[0]), "r"(b[1]));
}

// ---------------- small kernels (R1-proven) ----------------
__global__ void k_fill(float* __restrict__ out) {
    long long i = (long long)blockIdx.x * blockDim.x + threadIdx.x;
    if (i == 0) out[0] = 0.0f;
    if (i < B_) g_spos[i] = S_;
    long long stride = (long long)gridDim.x * blockDim.x;
    for (long long j = i; j < N_TAIL; j += stride)
        out[OFF_ROUT + j] = 0.0f;
}

__global__ void k_spos(const int* __restrict__ ids) {
    int i = blockIdx.x * blockDim.x + threadIdx.x;
    if (i < B_ * S_ && ids[i] == IMAGE_TOKEN_)
        atomicMin(&g_spos[i / S_], i % S_);
}

__global__ void k_text(const int* __restrict__ ids, const int* __restrict__ mask,
                       const int* __restrict__ labels, const float* __restrict__ table,
                       float* __restrict__ out) {
    int bs = blockIdx.x;
    int b = bs / S_, s = bs - b * S_;
    int id = ids[bs];
    if (id == IMAGE_TOKEN_) return;
    int sp = g_spos[b];
    int dest = s + (s > sp ? (NP_ - 1) : 0);
    const float* __restrict__ src = table + (long long)id * D_;
    float* __restrict__ dst = out + OFF_EMB + ((long long)b * MAXE_ + dest) * D_;
    for (int j = threadIdx.x; j < D_; j += blockDim.x)
        dst[j] = src[j];
    if (threadIdx.x == 0) {
        out[OFF_ATTN + (long long)b * MAXE_ + dest] = (float)mask[bs];
        out[OFF_LAB  + (long long)b * MAXE_ + dest] = (float)labels[bs];
    }
}

__global__ void k_imgmeta(float* __restrict__ out) {
    int i = blockIdx.x * blockDim.x + threadIdx.x;
    if (i >= B_ * NP_) return;
    int b = i / NP_, t = i - b * NP_;
    int dest = g_spos[b] + t;
    out[OFF_ATTN + (long long)b * MAXE_ + dest] = 1.0f;
    out[OFF_LAB  + (long long)b * MAXE_ + dest] = -100.0f;
}

// ---------------- fp32 -> fp16 weight conversion (elementwise) ----------------
__global__ void k_convh(const float* __restrict__ src, __half* __restrict__ dst, int n4) {
    int i = blockIdx.x * blockDim.x + threadIdx.x;
    long long stride = (long long)gridDim.x * blockDim.x;
    for (long long j = i; j < n4; j += stride) {
        float4 v = *(const float4*)(src + j * 4);
        __half2 a = __floats2half2_rn(v.x, v.y);
        __half2 b = __floats2half2_rn(v.z, v.w);
        uint2 pk = make_uint2(*(uint32_t*)&a, *(uint32_t*)&b);
        *(uint2*)(dst + j * 4) = pk;
    }
}

// ---------------- patch-embed GEMM (R1-proven math, fp16 output) ----------------
__global__ void __launch_bounds__(256)
k_patch(const float* __restrict__ pix, const float* __restrict__ Bw,
        const float* __restrict__ bias) {
    __shared__ float As[16][132];
    __shared__ float Bs[16][132];
    int t  = threadIdx.x;
    int m0 = blockIdx.y * 128;
    int n0 = blockIdx.x * 128;
    float acc[8][8] = {};
    int brow = t >> 5, bcol = t & 31;
    int rm = (t >> 4) * 8, rn = (t & 15) * 8;

    for (int k0 = 0; k0 < KPATCH_; k0 += 16) {
        #pragma unroll
        for (int i = 0; i < 8; i++) {
            int idx = t + 256 * i;
            int r  = idx >> 4;
            int kk = idx & 15;
            int k  = k0 + kk;
            float v = 0.0f;
            if (k < KPATCH_) {
                int m  = m0 + r;
                int ni = m / NP_;
                int tt = m - ni * NP_;
                int gi = tt / GRID_, gj = tt - gi * GRID_;
                int c  = k / 196;
                int rem = k - c * 196;
                int pi = rem / PATCH_, pj = rem - pi * PATCH_;
                long long addr = (((long long)ni * 3 + c) * IMG_ + gi * PATCH_ + pi) * IMG_
                               + gj * PATCH_ + pj;
                v = pix[addr];
            }
            As[kk][r] = v;
        }
        #pragma unroll
        for (int i = 0; i < 2; i++) {
            int kk = brow + i * 8;
            int k  = k0 + kk;
            float4 v = make_float4(0.f, 0.f, 0.f, 0.f);
            if (k < KPATCH_)
                v = *(const float4*)(Bw + (long long)k * DV_ + n0 + bcol * 4);
            *(float4*)(&Bs[kk][bcol * 4]) = v;
        }
        __syncthreads();
        #pragma unroll
        for (int k = 0; k < 16; k++) {
            float ra[8], rb[8];
            #pragma unroll
            for (int i = 0; i < 8; i++) ra[i] = As[k][rm + i];
            #pragma unroll
            for (int j = 0; j < 8; j++) rb[j] = Bs[k][rn + j];
            #pragma unroll
            for (int i = 0; i < 8; i++)
                #pragma unroll
                for (int j = 0; j < 8; j++)
                    acc[i][j] += ra[i] * rb[j];
        }
        __syncthreads();
    }
    #pragma unroll
    for (int i = 0; i < 8; i++) {
        int m = m0 + rm + i;
        #pragma unroll
        for (int j = 0; j < 8; j++) {
            int n = n0 + rn + j;
            g_hH[(size_t)m * DV_ + n] = __float2half(acc[i][j] + bias[n]);
        }
    }
}

// ---------------- TC GEMM — fp16 operands, cp.async double-buffer ----------------
// fp16 global sources, 48KB static smem (2 stages x 24KB — launch config proven by R9),
// cp.async overlaps chunk c+1 loads with chunk c compute.
// CTA 128(M) x 256(N), K-chunk 32, 8 warps 2x4, warp tile 64x64, mma.m16n8k16.f16.
// A smem: 128 rows x 64B, XOR key ((row>>1)&3)<<4. B smem: 32 k-rows x 512B, key (k&7)*16.
template<int EPI>
__global__ void __launch_bounds__(256)
k_tc(const float* __restrict__ bias, float* __restrict__ out) {
    constexpr int K = (EPI == 1) ? DV_ : D_;
    const __half* __restrict__ A  = (EPI == 1) ? g_hH : g_gH;
    const __half* __restrict__ WH = (EPI == 1) ? g_w1H : g_w2H;

    __shared__ __align__(16) char sa[2][8192];    // [stage] 128 rows x 64B
    __shared__ __align__(16) char sb[2][16384];   // [stage] 32 k-rows x 512B

    const int t = threadIdx.x, l = t & 31, wid = t >> 5;
    const int wm = wid >> 2, wn = wid & 3;
    const int m0 = blockIdx.y * 128;
    const int n0 = blockIdx.x * 256;

    float acc[4][8][4] = {};

    // async stage loader: A 2 x 16B, B 4 x 16B per thread (validated addressing)
    auto load_stage = [&](int st, int kc) {
        uint32_t saB = s2u(sa[st]), sbB = s2u(sb[st]);
        #pragma unroll
        for (int i = 0; i < 2; i++) {
            int idx = t + 256 * i;
            int row = idx >> 2, seg = idx & 3;
            uint32_t off = row * 64 + ((seg * 16) ^ (((row >> 1) & 3) << 4));
            cpasync16(saB + off, A + (size_t)(m0 + row) * K + kc + seg * 8);
        }
        #pragma unroll
        for (int i = 0; i < 4; i++) {
            int idx = t + 256 * i;
            int k = idx >> 5, seg = idx & 31;
            uint32_t off = k * 512 + ((seg * 16) ^ ((k & 7) * 16));
            cpasync16(sbB + off, WH + (size_t)(kc + k) * D_ + n0 + seg * 8);
        }
        asm volatile("cp.async.commit_group;" ::: "memory");
    };

    const int frow = l & 15, kb = ((l >> 4) & 1) * 16;
    const int bg = l >> 3, br = l & 7;
    const int bk = (bg & 1) * 8 + br;
    const int bnb = (bg >> 1) * 8;

    auto compute = [&](int st) {
        uint32_t saB = s2u(sa[st]), sbB = s2u(sb[st]);
        #pragma unroll
        for (int ks = 0; ks < 2; ks++) {
            uint32_t ah[4][4];
            #pragma unroll
            for (int mi = 0; mi < 4; mi++) {
                int row = wm * 64 + mi * 16 + frow;
                uint32_t off = row * 64 + ((ks * 32 + kb) ^ (((row >> 1) & 3) << 4));
                ldmx4(ah[mi], saB + off);
            }
            #pragma unroll
            for (int p = 0; p < 4; p++) {
                int nb = wn * 64 + p * 16 + bnb;
                int kr = ks * 16 + bk;
                uint32_t o = kr * 512 + ((nb * 2) ^ ((bk & 7) * 16));
                uint32_t rh[4];
                ldmx4t(rh, sbB + o);
                uint32_t b0[2] = { rh[0], rh[1] }, b1[2] = { rh[2], rh[3] };
                #pragma unroll
                for (int mi = 0; mi < 4; mi++) {
                    mma_f16(acc[mi][2*p],   ah[mi], b0);
                    mma_f16(acc[mi][2*p+1], ah[mi], b1);
                }
            }
        }
    };

    const int nch = K / 32;
    load_stage(0, 0);
    for (int c = 0; c < nch; c++) {
        if (c + 1 < nch) {
            load_stage((c + 1) & 1, (c + 1) * 32);     // overlaps compute(c)
            asm volatile("cp.async.wait_group 1;" ::: "memory");
        } else {
            asm volatile("cp.async.wait_group 0;" ::: "memory");
        }
        __syncthreads();        // chunk c data visible to all warps
        compute(c & 1);
        __syncthreads();        // all reads of buf c&1 done before it is refilled at c+1
    }

    // epilogue — EPI==2 rows start at OFF_EMB=1 (odd float offset): scalar stores only.
    const int lrow = l >> 2, lcol = (l & 3) * 2;
    #pragma unroll
    for (int mi = 0; mi < 4; mi++) {
        #pragma unroll
        for (int part = 0; part < 2; part++) {
            int m = m0 + wm * 64 + mi * 16 + lrow + part * 8;
            long long rowbase;
            if (EPI == 2) {
                int bb = m / NP_;
                int tt = m - bb * NP_;
                rowbase = OFF_EMB + ((long long)bb * MAXE_ + g_spos[bb] + tt) * (long long)D_;
            } else {
                rowbase = (long long)m * D_;
            }
            #pragma unroll
            for (int nj = 0; nj < 8; nj++) {
                int n = n0 + wn * 64 + nj * 8 + lcol;
                float v0 = acc[mi][nj][part * 2 + 0] + bias[n];
                float v1 = acc[mi][nj][part * 2 + 1] + bias[n + 1];
                if (EPI == 1) {
                    __half2 hh = __floats2half2_rn(gelu_tanh(v0), gelu_tanh(v1));
                    *(__half2*)&g_gH[rowbase + n] = hh;
                } else {
                    out[rowbase + n]     = v0;
                    out[rowbase + n + 1] = v1;
                }
            }
        }
    }
}

// ---------------- launch ----------------
extern "C" void kernel_launch(void* const* d_in, const int* in_sizes, int n_in,
                              void* d_out, int out_size) {
    const int*   ids     = (const int*)  d_in[0];
    const float* pix     = (const float*)d_in[1];
    const int*   mask    = (const int*)  d_in[2];
    const int*   labels  = (const int*)  d_in[3];
    const float* table   = (const float*)d_in[4];
    const float* patch_w = (const float*)d_in[6];
    const float* patch_b = (const float*)d_in[7];
    const float* w1      = (const float*)d_in[8];
    const float* b1      = (const float*)d_in[9];
    const float* w2      = (const float*)d_in[10];
    const float* b2      = (const float*)d_in[11];
    float* out = (float*)d_out;

    __half *w1H, *w2H;
    cudaGetSymbolAddress((void**)&w1H, g_w1H);
    cudaGetSymbolAddress((void**)&w2H, g_w2H);

    k_fill<<<512, 256>>>(out);
    k_spos<<<(B_ * S_ + 255) / 256, 256>>>(ids);
    k_text<<<B_ * S_, 256>>>(ids, mask, labels, table, out);
    k_imgmeta<<<(B_ * NP_ + 255) / 256, 256>>>(out);

    k_convh<<<2048, 256>>>(w1, w1H, (DV_ * D_) / 4);
    k_convh<<<8192, 256>>>(w2, w2H, (D_ * D_) / 4);

    k_patch<<<dim3(DV_ / 128, M_ / 128), 256>>>(pix, patch_w, patch_b);
    k_tc<1><<<dim3(D_ / 256, M_ / 128), 256>>>(b1, out);
    k_tc<2><<<dim3(D_ / 256, M_ / 128), 256>>>(b2, out);
}

// round 15
// speedup vs baseline: 1.8895x; 1.1699x over previous
#include <cuda_runtime.h>
#include <cuda_fp16.h>
#include <cstdint>

// ---------------- problem constants ----------------
#define B_        8
#define S_        1024
#define D_        4096
#define DV_       1024
#define IMG_      336
#define PATCH_    14
#define GRID_     24
#define NP_       576
#define MAXE_     1599
#define KPATCH_   588
#define KP_PAD    608          // 19 x 32 K-chunks, zero-padded tail
#define M_        (B_*NP_)     // 4608
#define IMAGE_TOKEN_ 32000

#define OFF_EMB   1LL
#define N_EMB     ((long long)B_*MAXE_*D_)
#define OFF_ATTN  (OFF_EMB + N_EMB)
#define OFF_LAB   (OFF_ATTN + (long long)B_*MAXE_)
#define OFF_ROUT  (OFF_LAB  + (long long)B_*MAXE_)
#define N_TAIL    (32LL*MAXE_*8 + 32LL*MAXE_*2)

// ---------------- device scratch ----------------
__device__ __half g_aH[(size_t)M_ * KP_PAD];   // patchified pixels (fp16)
__device__ __half g_wpH[(size_t)KP_PAD * DV_]; // patch_w fp16, [k][n], zero-padded
__device__ __half g_hH[(size_t)M_ * DV_];      // patch-embed output (fp16)
__device__ __half g_gH[(size_t)M_ * D_];       // gelu output (fp16)
__device__ __half g_w1H[(size_t)DV_ * D_];     // w1 fp16, [k][n]
__device__ __half g_w2H[(size_t)D_ * D_];      // w2 fp16, [k][n]
__device__ int    g_spos[B_];

__device__ __forceinline__ float gelu_tanh(float x) {
    float x3 = x * x * x;
    return 0.5f * x * (1.0f + tanhf(0.7978845608028654f * (x + 0.044715f * x3)));
}

__device__ __forceinline__ uint32_t s2u(const void* p) {
    return (uint32_t)__cvta_generic_to_shared(p);
}
__device__ __forceinline__ void cpasync16(uint32_t dst, const void* src) {
    asm volatile("cp.async.cg.shared.global [%0], [%1], 16;" :: "r"(dst), "l"(src) : "memory");
}
__device__ __forceinline__ void ldmx4(uint32_t* r, uint32_t addr) {
    asm volatile("ldmatrix.sync.aligned.m8n8.x4.shared.b16 {%0,%1,%2,%3}, [%4];"
                 : "=r"(r[0]), "=r"(r[1]), "=r"(r[2]), "=r"(r[3]) : "r"(addr) : "memory");
}
__device__ __forceinline__ void ldmx4t(uint32_t* r, uint32_t addr) {
    asm volatile("ldmatrix.sync.aligned.m8n8.x4.trans.shared.b16 {%0,%1,%2,%3}, [%4];"
                 : "=r"(r[0]), "=r"(r[1]), "=r"(r[2]), "=r"(r[3]) : "r"(addr) : "memory");
}
__device__ __forceinline__ void mma_f16(float* c, const uint32_t* a, const uint32_t* b) {
    asm volatile(
        "mma.sync.aligned.m16n8k16.row.col.f32.f16.f16.f32 "
        "{%0,%1,%2,%3}, {%4,%5,%6,%7}, {%8,%9}, {%0,%1,%2,%3};"
        : "+f"(c[0]), "+f"(c[1]), "+f"(c[2]), "+f"(c[3])
        : "r"(a[0]), "r"(a[1]), "r"(a[2]), "r"(a[3]), "r"(b[0]), "r"(b[1]));
}

// ---------------- small kernels (R1-proven) ----------------
__global__ void k_fill(float* __restrict__ out) {
    long long i = (long long)blockIdx.x * blockDim.x + threadIdx.x;
    if (i == 0) out[0] = 0.0f;
    if (i < B_) g_spos[i] = S_;
    long long stride = (long long)gridDim.x * blockDim.x;
    for (long long j = i; j < N_TAIL; j += stride)
        out[OFF_ROUT + j] = 0.0f;
}

__global__ void k_spos(const int* __restrict__ ids) {
    int i = blockIdx.x * blockDim.x + threadIdx.x;
    if (i < B_ * S_ && ids[i] == IMAGE_TOKEN_)
        atomicMin(&g_spos[i / S_], i % S_);
}

__global__ void k_text(const int* __restrict__ ids, const int* __restrict__ mask,
                       const int* __restrict__ labels, const float* __restrict__ table,
                       float* __restrict__ out) {
    int bs = blockIdx.x;
    int b = bs / S_, s = bs - b * S_;
    int id = ids[bs];
    if (id == IMAGE_TOKEN_) return;
    int sp = g_spos[b];
    int dest = s + (s > sp ? (NP_ - 1) : 0);
    const float* __restrict__ src = table + (long long)id * D_;
    float* __restrict__ dst = out + OFF_EMB + ((long long)b * MAXE_ + dest) * D_;
    for (int j = threadIdx.x; j < D_; j += blockDim.x)
        dst[j] = src[j];
    if (threadIdx.x == 0) {
        out[OFF_ATTN + (long long)b * MAXE_ + dest] = (float)mask[bs];
        out[OFF_LAB  + (long long)b * MAXE_ + dest] = (float)labels[bs];
    }
}

__global__ void k_imgmeta(float* __restrict__ out) {
    int i = blockIdx.x * blockDim.x + threadIdx.x;
    if (i >= B_ * NP_) return;
    int b = i / NP_, t = i - b * NP_;
    int dest = g_spos[b] + t;
    out[OFF_ATTN + (long long)b * MAXE_ + dest] = 1.0f;
    out[OFF_LAB  + (long long)b * MAXE_ + dest] = -100.0f;
}

// ---------------- conversions / gather ----------------
__global__ void k_convh(const float* __restrict__ src, __half* __restrict__ dst, int n4) {
    int i = blockIdx.x * blockDim.x + threadIdx.x;
    long long stride = (long long)gridDim.x * blockDim.x;
    for (long long j = i; j < n4; j += stride) {
        float4 v = *(const float4*)(src + j * 4);
        __half2 a = __floats2half2_rn(v.x, v.y);
        __half2 b = __floats2half2_rn(v.z, v.w);
        uint2 pk = make_uint2(*(uint32_t*)&a, *(uint32_t*)&b);
        *(uint2*)(dst + j * 4) = pk;
    }
}

// patch_w [588][1024] -> fp16 [608][1024] with zero rows for k >= 588
__global__ void k_convp(const float* __restrict__ w) {
    int idx = blockIdx.x * blockDim.x + threadIdx.x;
    if (idx >= KP_PAD * DV_) return;
    int k = idx / DV_;
    float v = (k < KPATCH_) ? w[idx] : 0.0f;
    g_wpH[idx] = __float2half(v);
}

// patchify pixels -> fp16 A matrix [4608][608], zero-padded K tail
__global__ void k_gather(const float* __restrict__ pix) {
    int idx = blockIdx.x * blockDim.x + threadIdx.x;
    if (idx >= M_ * KP_PAD) return;
    int m = idx / KP_PAD, k = idx - m * KP_PAD;
    float v = 0.0f;
    if (k < KPATCH_) {
        int ni = m / NP_, tt = m - ni * NP_;
        int gi = tt / GRID_, gj = tt - gi * GRID_;
        int c  = k / 196, rem = k - c * 196;
        int pi = rem / PATCH_, pj = rem - pi * PATCH_;
        long long addr = (((long long)ni * 3 + c) * IMG_ + gi * PATCH_ + pi) * IMG_
                       + gj * PATCH_ + pj;
        v = pix[addr];
    }
    g_aH[idx] = __float2half(v);
}

// ---------------- TC GEMM — fp16 operands, cp.async double-buffer ----------------
// EPI==0: A=g_aH (K=608), B=g_wpH (stride 1024) -> +bias -> g_hH
// EPI==1: A=g_hH (K=1024), B=g_w1H (stride 4096) -> gelu -> g_gH
// EPI==2: A=g_gH (K=4096), B=g_w2H (stride 4096) -> +bias -> scatter to out
// CTA 128(M) x 256(N), K-chunk 32, 8 warps 2x4, warp tile 64x64, mma.m16n8k16.f16.
template<int EPI>
__global__ void __launch_bounds__(256)
k_tc(const float* __restrict__ bias, float* __restrict__ out) {
    constexpr int K  = (EPI == 0) ? KP_PAD : (EPI == 1) ? DV_ : D_;
    constexpr int NS = (EPI == 0) ? DV_ : D_;   // B row stride
    const __half* __restrict__ A  = (EPI == 0) ? g_aH  : (EPI == 1) ? g_hH  : g_gH;
    const __half* __restrict__ WH = (EPI == 0) ? g_wpH : (EPI == 1) ? g_w1H : g_w2H;

    __shared__ __align__(16) char sa[2][8192];    // [stage] 128 rows x 64B
    __shared__ __align__(16) char sb[2][16384];   // [stage] 32 k-rows x 512B

    const int t = threadIdx.x, l = t & 31, wid = t >> 5;
    const int wm = wid >> 2, wn = wid & 3;
    const int m0 = blockIdx.y * 128;
    const int n0 = blockIdx.x * 256;

    float acc[4][8][4] = {};

    auto load_stage = [&](int st, int kc) {
        uint32_t saB = s2u(sa[st]), sbB = s2u(sb[st]);
        #pragma unroll
        for (int i = 0; i < 2; i++) {
            int idx = t + 256 * i;
            int row = idx >> 2, seg = idx & 3;
            uint32_t off = row * 64 + ((seg * 16) ^ (((row >> 1) & 3) << 4));
            cpasync16(saB + off, A + (size_t)(m0 + row) * K + kc + seg * 8);
        }
        #pragma unroll
        for (int i = 0; i < 4; i++) {
            int idx = t + 256 * i;
            int k = idx >> 5, seg = idx & 31;
            uint32_t off = k * 512 + ((seg * 16) ^ ((k & 7) * 16));
            cpasync16(sbB + off, WH + (size_t)(kc + k) * NS + n0 + seg * 8);
        }
        asm volatile("cp.async.commit_group;" ::: "memory");
    };

    const int frow = l & 15, kb = ((l >> 4) & 1) * 16;
    const int bg = l >> 3, br = l & 7;
    const int bk = (bg & 1) * 8 + br;
    const int bnb = (bg >> 1) * 8;

    auto compute = [&](int st) {
        uint32_t saB = s2u(sa[st]), sbB = s2u(sb[st]);
        #pragma unroll
        for (int ks = 0; ks < 2; ks++) {
            uint32_t ah[4][4];
            #pragma unroll
            for (int mi = 0; mi < 4; mi++) {
                int row = wm * 64 + mi * 16 + frow;
                uint32_t off = row * 64 + ((ks * 32 + kb) ^ (((row >> 1) & 3) << 4));
                ldmx4(ah[mi], saB + off);
            }
            #pragma unroll
            for (int p = 0; p < 4; p++) {
                int nb = wn * 64 + p * 16 + bnb;
                int kr = ks * 16 + bk;
                uint32_t o = kr * 512 + ((nb * 2) ^ ((bk & 7) * 16));
                uint32_t rh[4];
                ldmx4t(rh, sbB + o);
                uint32_t b0[2] = { rh[0], rh[1] }, b1[2] = { rh[2], rh[3] };
                #pragma unroll
                for (int mi = 0; mi < 4; mi++) {
                    mma_f16(acc[mi][2*p],   ah[mi], b0);
                    mma_f16(acc[mi][2*p+1], ah[mi], b1);
                }
            }
        }
    };

    const int nch = K / 32;
    load_stage(0, 0);
    for (int c = 0; c < nch; c++) {
        if (c + 1 < nch) {
            load_stage((c + 1) & 1, (c + 1) * 32);     // overlaps compute(c)
            asm volatile("cp.async.wait_group 1;" ::: "memory");
        } else {
            asm volatile("cp.async.wait_group 0;" ::: "memory");
        }
        __syncthreads();
        compute(c & 1);
        __syncthreads();
    }

    // epilogue — EPI==2 rows start at OFF_EMB=1 (odd float offset): scalar stores only.
    const int lrow = l >> 2, lcol = (l & 3) * 2;
    #pragma unroll
    for (int mi = 0; mi < 4; mi++) {
        #pragma unroll
        for (int part = 0; part < 2; part++) {
            int m = m0 + wm * 64 + mi * 16 + lrow + part * 8;
            long long rowbase;
            if (EPI == 2) {
                int bb = m / NP_;
                int tt = m - bb * NP_;
                rowbase = OFF_EMB + ((long long)bb * MAXE_ + g_spos[bb] + tt) * (long long)D_;
            } else if (EPI == 1) {
                rowbase = (long long)m * D_;
            } else {
                rowbase = (long long)m * DV_;
            }
            #pragma unroll
            for (int nj = 0; nj < 8; nj++) {
                int n = n0 + wn * 64 + nj * 8 + lcol;
                float v0 = acc[mi][nj][part * 2 + 0] + bias[n];
                float v1 = acc[mi][nj][part * 2 + 1] + bias[n + 1];
                if (EPI == 0) {
                    *(__half2*)&g_hH[rowbase + n] = __floats2half2_rn(v0, v1);
                } else if (EPI == 1) {
                    __half2 hh = __floats2half2_rn(gelu_tanh(v0), gelu_tanh(v1));
                    *(__half2*)&g_gH[rowbase + n] = hh;
                } else {
                    out[rowbase + n]     = v0;
                    out[rowbase + n + 1] = v1;
                }
            }
        }
    }
}

// ---------------- launch ----------------
extern "C" void kernel_launch(void* const* d_in, const int* in_sizes, int n_in,
                              void* d_out, int out_size) {
    const int*   ids     = (const int*)  d_in[0];
    const float* pix     = (const float*)d_in[1];
    const int*   mask    = (const int*)  d_in[2];
    const int*   labels  = (const int*)  d_in[3];
    const float* table   = (const float*)d_in[4];
    const float* patch_w = (const float*)d_in[6];
    const float* patch_b = (const float*)d_in[7];
    const float* w1      = (const float*)d_in[8];
    const float* b1      = (const float*)d_in[9];
    const float* w2      = (const float*)d_in[10];
    const float* b2      = (const float*)d_in[11];
    float* out = (float*)d_out;

    __half *w1H, *w2H;
    cudaGetSymbolAddress((void**)&w1H, g_w1H);
    cudaGetSymbolAddress((void**)&w2H, g_w2H);

    k_fill<<<512, 256>>>(out);
    k_spos<<<(B_ * S_ + 255) / 256, 256>>>(ids);
    k_text<<<B_ * S_, 256>>>(ids, mask, labels, table, out);
    k_imgmeta<<<(B_ * NP_ + 255) / 256, 256>>>(out);

    k_gather<<<(M_ * KP_PAD + 255) / 256, 256>>>(pix);
    k_convp<<<(KP_PAD * DV_ + 255) / 256, 256>>>(patch_w);
    k_convh<<<2048, 256>>>(w1, w1H, (DV_ * D_) / 4);
    k_convh<<<8192, 256>>>(w2, w2H, (D_ * D_) / 4);

    k_tc<0><<<dim3(DV_ / 256, M_ / 128), 256>>>(patch_b, out);
    k_tc<1><<<dim3(D_ / 256, M_ / 128), 256>>>(b1, out);
    k_tc<2><<<dim3(D_ / 256, M_ / 128), 256>>>(b2, out);
}

// round 16
// speedup vs baseline: 2.4054x; 1.2731x over previous
#include <cuda_runtime.h>
#include <cuda_fp16.h>
#include <cstdint>

// ---------------- problem constants ----------------
#define B_        8
#define S_        1024
#define D_        4096
#define DV_       1024
#define IMG_      336
#define PATCH_    14
#define GRID_     24
#define NP_       576
#define MAXE_     1599
#define KPATCH_   588
#define KP_PAD    608          // 19 x 32 K-chunks, zero-padded tail
#define M_        (B_*NP_)     // 4608
#define IMAGE_TOKEN_ 32000

#define OFF_EMB   1LL
#define N_EMB     ((long long)B_*MAXE_*D_)
#define OFF_ATTN  (OFF_EMB + N_EMB)
#define OFF_LAB   (OFF_ATTN + (long long)B_*MAXE_)
#define OFF_ROUT  (OFF_LAB  + (long long)B_*MAXE_)
#define N_TAIL    (32LL*MAXE_*8 + 32LL*MAXE_*2)

// ---------------- device scratch ----------------
__device__ __half g_aH[(size_t)M_ * KP_PAD];   // patchified pixels (fp16)
__device__ __half g_wpH[(size_t)KP_PAD * DV_]; // patch_w fp16, [k][n], zero-padded
__device__ __half g_hH[(size_t)M_ * DV_];      // patch-embed output (fp16)
__device__ __half g_gH[(size_t)M_ * D_];       // gelu output (fp16)
__device__ __half g_w1H[(size_t)DV_ * D_];     // w1 fp16, [k][n]
__device__ __half g_w2H[(size_t)D_ * D_];      // w2 fp16, [k][n]
__device__ int    g_spos[B_];

__device__ __forceinline__ float gelu_tanh(float x) {
    float x3 = x * x * x;
    return 0.5f * x * (1.0f + tanhf(0.7978845608028654f * (x + 0.044715f * x3)));
}

__device__ __forceinline__ uint32_t s2u(const void* p) {
    return (uint32_t)__cvta_generic_to_shared(p);
}
__device__ __forceinline__ void cpasync16(uint32_t dst, const void* src) {
    asm volatile("cp.async.cg.shared.global [%0], [%1], 16;" :: "r"(dst), "l"(src) : "memory");
}
__device__ __forceinline__ void ldmx4(uint32_t* r, uint32_t addr) {
    asm volatile("ldmatrix.sync.aligned.m8n8.x4.shared.b16 {%0,%1,%2,%3}, [%4];"
                 : "=r"(r[0]), "=r"(r[1]), "=r"(r[2]), "=r"(r[3]) : "r"(addr) : "memory");
}
__device__ __forceinline__ void ldmx4t(uint32_t* r, uint32_t addr) {
    asm volatile("ldmatrix.sync.aligned.m8n8.x4.trans.shared.b16 {%0,%1,%2,%3}, [%4];"
                 : "=r"(r[0]), "=r"(r[1]), "=r"(r[2]), "=r"(r[3]) : "r"(addr) : "memory");
}
__device__ __forceinline__ void mma_f16(float* c, const uint32_t* a, const uint32_t* b) {
    asm volatile(
        "mma.sync.aligned.m16n8k16.row.col.f32.f16.f16.f32 "
        "{%0,%1,%2,%3}, {%4,%5,%6,%7}, {%8,%9}, {%0,%1,%2,%3};"
        : "+f"(c[0]), "+f"(c[1]), "+f"(c[2]), "+f"(c[3])
        : "r"(a[0]), "r"(a[1]), "r"(a[2]), "r"(a[3]), "r"(b[0]), "r"(b[1]));
}

// ---------------- small kernels (R1-proven) ----------------
__global__ void k_fill(float* __restrict__ out) {
    long long i = (long long)blockIdx.x * blockDim.x + threadIdx.x;
    if (i == 0) out[0] = 0.0f;
    if (i < B_) g_spos[i] = S_;
    long long stride = (long long)gridDim.x * blockDim.x;
    for (long long j = i; j < N_TAIL; j += stride)
        out[OFF_ROUT + j] = 0.0f;
}

__global__ void k_spos(const int* __restrict__ ids) {
    int i = blockIdx.x * blockDim.x + threadIdx.x;
    if (i < B_ * S_ && ids[i] == IMAGE_TOKEN_)
        atomicMin(&g_spos[i / S_], i % S_);
}

__global__ void k_text(const int* __restrict__ ids, const int* __restrict__ mask,
                       const int* __restrict__ labels, const float* __restrict__ table,
                       float* __restrict__ out) {
    int bs = blockIdx.x;
    int b = bs / S_, s = bs - b * S_;
    int id = ids[bs];
    if (id == IMAGE_TOKEN_) return;
    int sp = g_spos[b];
    int dest = s + (s > sp ? (NP_ - 1) : 0);
    const float* __restrict__ src = table + (long long)id * D_;
    float* __restrict__ dst = out + OFF_EMB + ((long long)b * MAXE_ + dest) * D_;
    for (int j = threadIdx.x; j < D_; j += blockDim.x)
        dst[j] = src[j];
    if (threadIdx.x == 0) {
        out[OFF_ATTN + (long long)b * MAXE_ + dest] = (float)mask[bs];
        out[OFF_LAB  + (long long)b * MAXE_ + dest] = (float)labels[bs];
    }
}

__global__ void k_imgmeta(float* __restrict__ out) {
    int i = blockIdx.x * blockDim.x + threadIdx.x;
    if (i >= B_ * NP_) return;
    int b = i / NP_, t = i - b * NP_;
    int dest = g_spos[b] + t;
    out[OFF_ATTN + (long long)b * MAXE_ + dest] = 1.0f;
    out[OFF_LAB  + (long long)b * MAXE_ + dest] = -100.0f;
}

// ---------------- conversions / gather ----------------
__global__ void k_convh(const float* __restrict__ src, __half* __restrict__ dst, int n4) {
    int i = blockIdx.x * blockDim.x + threadIdx.x;
    long long stride = (long long)gridDim.x * blockDim.x;
    for (long long j = i; j < n4; j += stride) {
        float4 v = *(const float4*)(src + j * 4);
        __half2 a = __floats2half2_rn(v.x, v.y);
        __half2 b = __floats2half2_rn(v.z, v.w);
        uint2 pk = make_uint2(*(uint32_t*)&a, *(uint32_t*)&b);
        *(uint2*)(dst + j * 4) = pk;
    }
}

// patch_w [588][1024] -> fp16 [608][1024] with zero rows for k >= 588
__global__ void k_convp(const float* __restrict__ w) {
    int idx = blockIdx.x * blockDim.x + threadIdx.x;
    if (idx >= KP_PAD * DV_) return;
    int k = idx / DV_;
    float v = (k < KPATCH_) ? w[idx] : 0.0f;
    g_wpH[idx] = __float2half(v);
}

// patchify pixels -> fp16 A matrix [4608][608], zero-padded K tail
__global__ void k_gather(const float* __restrict__ pix) {
    int idx = blockIdx.x * blockDim.x + threadIdx.x;
    if (idx >= M_ * KP_PAD) return;
    int m = idx / KP_PAD, k = idx - m * KP_PAD;
    float v = 0.0f;
    if (k < KPATCH_) {
        int ni = m / NP_, tt = m - ni * NP_;
        int gi = tt / GRID_, gj = tt - gi * GRID_;
        int c  = k / 196, rem = k - c * 196;
        int pi = rem / PATCH_, pj = rem - pi * PATCH_;
        long long addr = (((long long)ni * 3 + c) * IMG_ + gi * PATCH_ + pi) * IMG_
                       + gj * PATCH_ + pj;
        v = pix[addr];
    }
    g_aH[idx] = __float2half(v);
}

// ---------------- TC GEMM — 128x128 CTA, 128 threads, 2 CTAs/SM ----------------
// fp16 operands, cp.async double-buffer, 32KB static smem (2 stages x 16KB).
// 4 warps 2x2, warp tile 64x64, mma.m16n8k16.f16. K-chunk 32, K order unchanged
// vs R15 (bit-identical accumulation).
// A smem: 128 rows x 64B, XOR key ((row>>1)&3)<<4.
// B smem: 32 k-rows x 256B, XOR key (k&7)*16.
template<int EPI>
__global__ void __launch_bounds__(128, 2)
k_tc(const float* __restrict__ bias, float* __restrict__ out) {
    constexpr int K  = (EPI == 0) ? KP_PAD : (EPI == 1) ? DV_ : D_;
    constexpr int NS = (EPI == 0) ? DV_ : D_;   // B row stride
    const __half* __restrict__ A  = (EPI == 0) ? g_aH  : (EPI == 1) ? g_hH  : g_gH;
    const __half* __restrict__ WH = (EPI == 0) ? g_wpH : (EPI == 1) ? g_w1H : g_w2H;

    __shared__ __align__(16) char sa[2][8192];   // [stage] 128 rows x 64B
    __shared__ __align__(16) char sb[2][8192];   // [stage] 32 k-rows x 256B

    const int t = threadIdx.x, l = t & 31, wid = t >> 5;
    const int wm = wid >> 1, wn = wid & 1;       // 2x2 warp grid
    const int m0 = blockIdx.y * 128;
    const int n0 = blockIdx.x * 128;

    float acc[4][8][4] = {};

    // async stage loader: A 4 x 16B, B 4 x 16B per thread
    auto load_stage = [&](int st, int kc) {
        uint32_t saB = s2u(sa[st]), sbB = s2u(sb[st]);
        #pragma unroll
        for (int i = 0; i < 4; i++) {
            int idx = t + 128 * i;
            int row = idx >> 2, seg = idx & 3;
            uint32_t off = row * 64 + ((seg * 16) ^ (((row >> 1) & 3) << 4));
            cpasync16(saB + off, A + (size_t)(m0 + row) * K + kc + seg * 8);
        }
        #pragma unroll
        for (int i = 0; i < 4; i++) {
            int idx = t + 128 * i;
            int k = idx >> 4, seg = idx & 15;
            uint32_t off = k * 256 + ((seg * 16) ^ ((k & 7) * 16));
            cpasync16(sbB + off, WH + (size_t)(kc + k) * NS + n0 + seg * 8);
        }
        asm volatile("cp.async.commit_group;" ::: "memory");
    };

    const int frow = l & 15, kb = ((l >> 4) & 1) * 16;
    const int bg = l >> 3, br = l & 7;
    const int bk = (bg & 1) * 8 + br;
    const int bnb = (bg >> 1) * 8;

    auto compute = [&](int st) {
        uint32_t saB = s2u(sa[st]), sbB = s2u(sb[st]);
        #pragma unroll
        for (int ks = 0; ks < 2; ks++) {
            uint32_t ah[4][4];
            #pragma unroll
            for (int mi = 0; mi < 4; mi++) {
                int row = wm * 64 + mi * 16 + frow;
                uint32_t off = row * 64 + ((ks * 32 + kb) ^ (((row >> 1) & 3) << 4));
                ldmx4(ah[mi], saB + off);
            }
            #pragma unroll
            for (int p = 0; p < 4; p++) {
                int nb = wn * 64 + p * 16 + bnb;
                int kr = ks * 16 + bk;
                uint32_t o = kr * 256 + ((nb * 2) ^ ((bk & 7) * 16));
                uint32_t rh[4];
                ldmx4t(rh, sbB + o);
                uint32_t b0[2] = { rh[0], rh[1] }, b1[2] = { rh[2], rh[3] };
                #pragma unroll
                for (int mi = 0; mi < 4; mi++) {
                    mma_f16(acc[mi][2*p],   ah[mi], b0);
                    mma_f16(acc[mi][2*p+1], ah[mi], b1);
                }
            }
        }
    };

    const int nch = K / 32;
    load_stage(0, 0);
    for (int c = 0; c < nch; c++) {
        if (c + 1 < nch) {
            load_stage((c + 1) & 1, (c + 1) * 32);     // overlaps compute(c)
            asm volatile("cp.async.wait_group 1;" ::: "memory");
        } else {
            asm volatile("cp.async.wait_group 0;" ::: "memory");
        }
        __syncthreads();
        compute(c & 1);
        __syncthreads();
    }

    // epilogue — EPI==2 rows start at OFF_EMB=1 (odd float offset): scalar stores only.
    const int lrow = l >> 2, lcol = (l & 3) * 2;
    #pragma unroll
    for (int mi = 0; mi < 4; mi++) {
        #pragma unroll
        for (int part = 0; part < 2; part++) {
            int m = m0 + wm * 64 + mi * 16 + lrow + part * 8;
            long long rowbase;
            if (EPI == 2) {
                int bb = m / NP_;
                int tt = m - bb * NP_;
                rowbase = OFF_EMB + ((long long)bb * MAXE_ + g_spos[bb] + tt) * (long long)D_;
            } else if (EPI == 1) {
                rowbase = (long long)m * D_;
            } else {
                rowbase = (long long)m * DV_;
            }
            #pragma unroll
            for (int nj = 0; nj < 8; nj++) {
                int n = n0 + wn * 64 + nj * 8 + lcol;
                float v0 = acc[mi][nj][part * 2 + 0] + bias[n];
                float v1 = acc[mi][nj][part * 2 + 1] + bias[n + 1];
                if (EPI == 0) {
                    *(__half2*)&g_hH[rowbase + n] = __floats2half2_rn(v0, v1);
                } else if (EPI == 1) {
                    __half2 hh = __floats2half2_rn(gelu_tanh(v0), gelu_tanh(v1));
                    *(__half2*)&g_gH[rowbase + n] = hh;
                } else {
                    out[rowbase + n]     = v0;
                    out[rowbase + n + 1] = v1;
                }
            }
        }
    }
}

// ---------------- launch ----------------
extern "C" void kernel_launch(void* const* d_in, const int* in_sizes, int n_in,
                              void* d_out, int out_size) {
    const int*   ids     = (const int*)  d_in[0];
    const float* pix     = (const float*)d_in[1];
    const int*   mask    = (const int*)  d_in[2];
    const int*   labels  = (const int*)  d_in[3];
    const float* table   = (const float*)d_in[4];
    const float* patch_w = (const float*)d_in[6];
    const float* patch_b = (const float*)d_in[7];
    const float* w1      = (const float*)d_in[8];
    const float* b1      = (const float*)d_in[9];
    const float* w2      = (const float*)d_in[10];
    const float* b2      = (const float*)d_in[11];
    float* out = (float*)d_out;

    __half *w1H, *w2H;
    cudaGetSymbolAddress((void**)&w1H, g_w1H);
    cudaGetSymbolAddress((void**)&w2H, g_w2H);

    k_fill<<<512, 256>>>(out);
    k_spos<<<(B_ * S_ + 255) / 256, 256>>>(ids);
    k_text<<<B_ * S_, 256>>>(ids, mask, labels, table, out);
    k_imgmeta<<<(B_ * NP_ + 255) / 256, 256>>>(out);

    k_gather<<<(M_ * KP_PAD + 255) / 256, 256>>>(pix);
    k_convp<<<(KP_PAD * DV_ + 255) / 256, 256>>>(patch_w);
    k_convh<<<2048, 256>>>(w1, w1H, (DV_ * D_) / 4);
    k_convh<<<8192, 256>>>(w2, w2H, (D_ * D_) / 4);

    k_tc<0><<<dim3(DV_ / 128, M_ / 128), 128>>>(patch_b, out);
    k_tc<1><<<dim3(D_ / 128, M_ / 128), 128>>>(b1, out);
    k_tc<2><<<dim3(D_ / 128, M_ / 128), 128>>>(b2, out);
}

// round 17
// speedup vs baseline: 2.4403x; 1.0145x over previous
#include <cuda_runtime.h>
#include <cuda_fp16.h>
#include <cstdint>

// ---------------- problem constants ----------------
#define B_        8
#define S_        1024
#define D_        4096
#define DV_       1024
#define IMG_      336
#define PATCH_    14
#define GRID_     24
#define NP_       576
#define MAXE_     1599
#define KPATCH_   588
#define KP_PAD    608          // 19 x 32 K-chunks, zero-padded tail
#define M_        (B_*NP_)     // 4608
#define IMAGE_TOKEN_ 32000

#define OFF_EMB   1LL
#define N_EMB     ((long long)B_*MAXE_*D_)
#define OFF_ATTN  (OFF_EMB + N_EMB)
#define OFF_LAB   (OFF_ATTN + (long long)B_*MAXE_)
#define OFF_ROUT  (OFF_LAB  + (long long)B_*MAXE_)
#define N_TAIL    (32LL*MAXE_*8 + 32LL*MAXE_*2)

// ---------------- device scratch ----------------
__device__ __half g_aH[(size_t)M_ * KP_PAD];   // patchified pixels (fp16)
__device__ __half g_wpH[(size_t)KP_PAD * DV_]; // patch_w fp16, [k][n], zero-padded
__device__ __half g_hH[(size_t)M_ * DV_];      // patch-embed output (fp16)
__device__ __half g_gH[(size_t)M_ * D_];       // gelu output (fp16)
__device__ __half g_w1H[(size_t)DV_ * D_];     // w1 fp16, [k][n]
__device__ __half g_w2H[(size_t)D_ * D_];      // w2 fp16, [k][n]
__device__ int    g_spos[B_];

__device__ __forceinline__ float gelu_tanh(float x) {
    float x3 = x * x * x;
    return 0.5f * x * (1.0f + tanhf(0.7978845608028654f * (x + 0.044715f * x3)));
}

__device__ __forceinline__ uint32_t s2u(const void* p) {
    return (uint32_t)__cvta_generic_to_shared(p);
}
__device__ __forceinline__ void cpasync16(uint32_t dst, const void* src) {
    asm volatile("cp.async.cg.shared.global [%0], [%1], 16;" :: "r"(dst), "l"(src) : "memory");
}
__device__ __forceinline__ void ldmx4(uint32_t* r, uint32_t addr) {
    asm volatile("ldmatrix.sync.aligned.m8n8.x4.shared.b16 {%0,%1,%2,%3}, [%4];"
                 : "=r"(r[0]), "=r"(r[1]), "=r"(r[2]), "=r"(r[3]) : "r"(addr) : "memory");
}
__device__ __forceinline__ void ldmx4t(uint32_t* r, uint32_t addr) {
    asm volatile("ldmatrix.sync.aligned.m8n8.x4.trans.shared.b16 {%0,%1,%2,%3}, [%4];"
                 : "=r"(r[0]), "=r"(r[1]), "=r"(r[2]), "=r"(r[3]) : "r"(addr) : "memory");
}
__device__ __forceinline__ void mma_f16(float* c, const uint32_t* a, const uint32_t* b) {
    asm volatile(
        "mma.sync.aligned.m16n8k16.row.col.f32.f16.f16.f32 "
        "{%0,%1,%2,%3}, {%4,%5,%6,%7}, {%8,%9}, {%0,%1,%2,%3};"
        : "+f"(c[0]), "+f"(c[1]), "+f"(c[2]), "+f"(c[3])
        : "r"(a[0]), "r"(a[1]), "r"(a[2]), "r"(a[3]), "r"(b[0]), "r"(b[1]));
}

// ---------------- small kernels (R1-proven) ----------------
__global__ void k_fill(float* __restrict__ out) {
    long long i = (long long)blockIdx.x * blockDim.x + threadIdx.x;
    if (i == 0) out[0] = 0.0f;
    if (i < B_) g_spos[i] = S_;
    long long stride = (long long)gridDim.x * blockDim.x;
    for (long long j = i; j < N_TAIL; j += stride)
        out[OFF_ROUT + j] = 0.0f;
}

__global__ void k_spos(const int* __restrict__ ids) {
    int i = blockIdx.x * blockDim.x + threadIdx.x;
    if (i < B_ * S_ && ids[i] == IMAGE_TOKEN_)
        atomicMin(&g_spos[i / S_], i % S_);
}

__global__ void k_text(const int* __restrict__ ids, const int* __restrict__ mask,
                       const int* __restrict__ labels, const float* __restrict__ table,
                       float* __restrict__ out) {
    int bs = blockIdx.x;
    int b = bs / S_, s = bs - b * S_;
    int id = ids[bs];
    if (id == IMAGE_TOKEN_) return;
    int sp = g_spos[b];
    int dest = s + (s > sp ? (NP_ - 1) : 0);
    const float* __restrict__ src = table + (long long)id * D_;
    float* __restrict__ dst = out + OFF_EMB + ((long long)b * MAXE_ + dest) * D_;
    for (int j = threadIdx.x; j < D_; j += blockDim.x)
        dst[j] = src[j];
    if (threadIdx.x == 0) {
        out[OFF_ATTN + (long long)b * MAXE_ + dest] = (float)mask[bs];
        out[OFF_LAB  + (long long)b * MAXE_ + dest] = (float)labels[bs];
    }
}

__global__ void k_imgmeta(float* __restrict__ out) {
    int i = blockIdx.x * blockDim.x + threadIdx.x;
    if (i >= B_ * NP_) return;
    int b = i / NP_, t = i - b * NP_;
    int dest = g_spos[b] + t;
    out[OFF_ATTN + (long long)b * MAXE_ + dest] = 1.0f;
    out[OFF_LAB  + (long long)b * MAXE_ + dest] = -100.0f;
}

// ---------------- conversions / gather ----------------
__global__ void k_convh(const float* __restrict__ src, __half* __restrict__ dst, int n4) {
    int i = blockIdx.x * blockDim.x + threadIdx.x;
    long long stride = (long long)gridDim.x * blockDim.x;
    for (long long j = i; j < n4; j += stride) {
        float4 v = *(const float4*)(src + j * 4);
        __half2 a = __floats2half2_rn(v.x, v.y);
        __half2 b = __floats2half2_rn(v.z, v.w);
        uint2 pk = make_uint2(*(uint32_t*)&a, *(uint32_t*)&b);
        *(uint2*)(dst + j * 4) = pk;
    }
}

// patch_w [588][1024] -> fp16 [608][1024] with zero rows for k >= 588
__global__ void k_convp(const float* __restrict__ w) {
    int idx = blockIdx.x * blockDim.x + threadIdx.x;
    if (idx >= KP_PAD * DV_) return;
    int k = idx / DV_;
    float v = (k < KPATCH_) ? w[idx] : 0.0f;
    g_wpH[idx] = __float2half(v);
}

// patchify pixels -> fp16 A matrix [4608][608], zero-padded K tail
__global__ void k_gather(const float* __restrict__ pix) {
    int idx = blockIdx.x * blockDim.x + threadIdx.x;
    if (idx >= M_ * KP_PAD) return;
    int m = idx / KP_PAD, k = idx - m * KP_PAD;
    float v = 0.0f;
    if (k < KPATCH_) {
        int ni = m / NP_, tt = m - ni * NP_;
        int gi = tt / GRID_, gj = tt - gi * GRID_;
        int c  = k / 196, rem = k - c * 196;
        int pi = rem / PATCH_, pj = rem - pi * PATCH_;
        long long addr = (((long long)ni * 3 + c) * IMG_ + gi * PATCH_ + pi) * IMG_
                       + gj * PATCH_ + pj;
        v = pix[addr];
    }
    g_aH[idx] = __float2half(v);
}

// ---------------- TC GEMM — 3-stage cp.async, ONE sync per chunk, 2 CTAs/SM ----------------
// fp16 operands, 48KB static smem (3 stages x 16KB). Hazard chain: sync(c) orders all
// compute(c-1) before loads for c+2 target stage (c+2)%3 == (c-1)%3.
// CTA 128x128, 128 threads, 4 warps 2x2, warp tile 64x64, K-chunk 32 (order unchanged
// vs R16 -> bit-identical accumulation).
// A smem: 128 rows x 64B, XOR key ((row>>1)&3)<<4. B smem: 32 k-rows x 256B, key (k&7)*16.
template<int EPI>
__global__ void __launch_bounds__(128, 2)
k_tc(const float* __restrict__ bias, float* __restrict__ out) {
    constexpr int K  = (EPI == 0) ? KP_PAD : (EPI == 1) ? DV_ : D_;
    constexpr int NS = (EPI == 0) ? DV_ : D_;   // B row stride
    const __half* __restrict__ A  = (EPI == 0) ? g_aH  : (EPI == 1) ? g_hH  : g_gH;
    const __half* __restrict__ WH = (EPI == 0) ? g_wpH : (EPI == 1) ? g_w1H : g_w2H;

    __shared__ __align__(16) char sa[3][8192];   // [stage] 128 rows x 64B
    __shared__ __align__(16) char sb[3][8192];   // [stage] 32 k-rows x 256B

    const int t = threadIdx.x, l = t & 31, wid = t >> 5;
    const int wm = wid >> 1, wn = wid & 1;       // 2x2 warp grid
    const int m0 = blockIdx.y * 128;
    const int n0 = blockIdx.x * 128;

    float acc[4][8][4] = {};

    auto load_stage = [&](int st, int kc) {
        uint32_t saB = s2u(sa[st]), sbB = s2u(sb[st]);
        #pragma unroll
        for (int i = 0; i < 4; i++) {
            int idx = t + 128 * i;
            int row = idx >> 2, seg = idx & 3;
            uint32_t off = row * 64 + ((seg * 16) ^ (((row >> 1) & 3) << 4));
            cpasync16(saB + off, A + (size_t)(m0 + row) * K + kc + seg * 8);
        }
        #pragma unroll
        for (int i = 0; i < 4; i++) {
            int idx = t + 128 * i;
            int k = idx >> 4, seg = idx & 15;
            uint32_t off = k * 256 + ((seg * 16) ^ ((k & 7) * 16));
            cpasync16(sbB + off, WH + (size_t)(kc + k) * NS + n0 + seg * 8);
        }
        asm volatile("cp.async.commit_group;" ::: "memory");
    };

    const int frow = l & 15, kb = ((l >> 4) & 1) * 16;
    const int bg = l >> 3, br = l & 7;
    const int bk = (bg & 1) * 8 + br;
    const int bnb = (bg >> 1) * 8;

    auto compute = [&](int st) {
        uint32_t saB = s2u(sa[st]), sbB = s2u(sb[st]);
        #pragma unroll
        for (int ks = 0; ks < 2; ks++) {
            uint32_t ah[4][4];
            #pragma unroll
            for (int mi = 0; mi < 4; mi++) {
                int row = wm * 64 + mi * 16 + frow;
                uint32_t off = row * 64 + ((ks * 32 + kb) ^ (((row >> 1) & 3) << 4));
                ldmx4(ah[mi], saB + off);
            }
            #pragma unroll
            for (int p = 0; p < 4; p++) {
                int nb = wn * 64 + p * 16 + bnb;
                int kr = ks * 16 + bk;
                uint32_t o = kr * 256 + ((nb * 2) ^ ((bk & 7) * 16));
                uint32_t rh[4];
                ldmx4t(rh, sbB + o);
                uint32_t b0[2] = { rh[0], rh[1] }, b1[2] = { rh[2], rh[3] };
                #pragma unroll
                for (int mi = 0; mi < 4; mi++) {
                    mma_f16(acc[mi][2*p],   ah[mi], b0);
                    mma_f16(acc[mi][2*p+1], ah[mi], b1);
                }
            }
        }
    };

    const int nch = K / 32;   // 19, 32, or 128 (always >= 3)
    int st = 0;               // stage of chunk c (c % 3)
    load_stage(0, 0);
    load_stage(1, 32);
    for (int c = 0; c < nch; c++) {
        // wait until stage c's group has landed (own groups), then publish to all warps
        if (c + 1 < nch) {
            asm volatile("cp.async.wait_group 1;" ::: "memory");
        } else {
            asm volatile("cp.async.wait_group 0;" ::: "memory");
        }
        __syncthreads();                 // stage c visible; all warps done compute(c-1)
        compute(st);
        if (c + 2 < nch) {               // fill stage (c+2)%3 == (c-1)%3 (readers passed sync)
            int st2 = st + 2 - ((st >= 1) ? 3 : 0);   // (st+2)%3
            load_stage(st2, (c + 2) * 32);
        }
        st = (st + 1 == 3) ? 0 : st + 1;
    }

    // epilogue — EPI==2 rows start at OFF_EMB=1 (odd float offset): scalar stores only.
    const int lrow = l >> 2, lcol = (l & 3) * 2;
    #pragma unroll
    for (int mi = 0; mi < 4; mi++) {
        #pragma unroll
        for (int part = 0; part < 2; part++) {
            int m = m0 + wm * 64 + mi * 16 + lrow + part * 8;
            long long rowbase;
            if (EPI == 2) {
                int bb = m / NP_;
                int tt = m - bb * NP_;
                rowbase = OFF_EMB + ((long long)bb * MAXE_ + g_spos[bb] + tt) * (long long)D_;
            } else if (EPI == 1) {
                rowbase = (long long)m * D_;
            } else {
                rowbase = (long long)m * DV_;
            }
            #pragma unroll
            for (int nj = 0; nj < 8; nj++) {
                int n = n0 + wn * 64 + nj * 8 + lcol;
                float v0 = acc[mi][nj][part * 2 + 0] + bias[n];
                float v1 = acc[mi][nj][part * 2 + 1] + bias[n + 1];
                if (EPI == 0) {
                    *(__half2*)&g_hH[rowbase + n] = __floats2half2_rn(v0, v1);
                } else if (EPI == 1) {
                    __half2 hh = __floats2half2_rn(gelu_tanh(v0), gelu_tanh(v1));
                    *(__half2*)&g_gH[rowbase + n] = hh;
                } else {
                    out[rowbase + n]     = v0;
                    out[rowbase + n + 1] = v1;
                }
            }
        }
    }
}

// ---------------- launch ----------------
extern "C" void kernel_launch(void* const* d_in, const int* in_sizes, int n_in,
                              void* d_out, int out_size) {
    const int*   ids     = (const int*)  d_in[0];
    const float* pix     = (const float*)d_in[1];
    const int*   mask    = (const int*)  d_in[2];
    const int*   labels  = (const int*)  d_in[3];
    const float* table   = (const float*)d_in[4];
    const float* patch_w = (const float*)d_in[6];
    const float* patch_b = (const float*)d_in[7];
    const float* w1      = (const float*)d_in[8];
    const float* b1      = (const float*)d_in[9];
    const float* w2      = (const float*)d_in[10];
    const float* b2      = (const float*)d_in[11];
    float* out = (float*)d_out;

    __half *w1H, *w2H;
    cudaGetSymbolAddress((void**)&w1H, g_w1H);
    cudaGetSymbolAddress((void**)&w2H, g_w2H);

    k_fill<<<512, 256>>>(out);
    k_spos<<<(B_ * S_ + 255) / 256, 256>>>(ids);
    k_text<<<B_ * S_, 256>>>(ids, mask, labels, table, out);
    k_imgmeta<<<(B_ * NP_ + 255) / 256, 256>>>(out);

    k_gather<<<(M_ * KP_PAD + 255) / 256, 256>>>(pix);
    k_convp<<<(KP_PAD * DV_ + 255) / 256, 256>>>(patch_w);
    k_convh<<<2048, 256>>>(w1, w1H, (DV_ * D_) / 4);
    k_convh<<<8192, 256>>>(w2, w2H, (D_ * D_) / 4);

    k_tc<0><<<dim3(DV_ / 128, M_ / 128), 128>>>(patch_b, out);
    k_tc<1><<<dim3(D_ / 128, M_ / 128), 128>>>(b1, out);
    k_tc<2><<<dim3(D_ / 128, M_ / 128), 128>>>(b2, out);
}